// round 1
// baseline (speedup 1.0000x reference)
#include <cuda_runtime.h>

// ----------------------------------------------------------------------------
// SpecAttn: out = softmax((xWq+bq)(xWk+bk)^T / sqrt(H)) (xWv+bv) Wo + bo
// B=8, S=2048, N_INP=N_HID=N_OUT=1024. All fp32.
//
// Round 0: fp32 CUDA-core tiled SGEMM baseline (tensor-core tf32 port comes
// next). 5 GEMMs + 1 softmax. Scratch in __device__ globals (no allocs).
// ----------------------------------------------------------------------------

#define BM 128
#define BN 128
#define BK 16
#define NTHREADS 256

// Scratch (B*S*H = 16,777,216 floats = 64 MB each; E = 128 MB)
__device__ float g_q[8L * 2048 * 1024];
__device__ float g_k[8L * 2048 * 1024];
__device__ float g_v[8L * 2048 * 1024];
__device__ float g_ctx[8L * 2048 * 1024];
__device__ float g_e[8L * 2048 * 2048];

// ----------------------------------------------------------------------------
// Tiled SGEMM: C[b] = alpha * A[b] @ B[b](^T) + bias
//   A: [M,K] row-major.
//   BNT=false: B is [K,N] row-major (NN). BNT=true: B is [N,K] row-major (NT).
//   All of M,N multiples of 128, K multiple of 16 (true for every call here).
// ----------------------------------------------------------------------------
template <bool BNT, bool HAS_BIAS>
__global__ __launch_bounds__(NTHREADS, 2)
void sgemm_kernel(const float* __restrict__ A,
                  const float* __restrict__ B,
                  const float* __restrict__ bias,
                  float* __restrict__ C,
                  int M, int N, int K,
                  long strideA, long strideB, long strideC,
                  float alpha)
{
    __shared__ float As[BK][BM + 4];
    __shared__ float Bs[BK][BN + 4];

    const int zb = blockIdx.z;
    A += (long)zb * strideA;
    B += (long)zb * strideB;
    C += (long)zb * strideC;

    const int tid = threadIdx.x;
    const int tx = tid & 15;   // 0..15 -> column groups
    const int ty = tid >> 4;   // 0..15 -> row groups

    const int rowBase = blockIdx.y * BM;
    const int colBase = blockIdx.x * BN;

    // --- A tile load mapping: transpose [BM x BK] into As[k][m] ---
    const int a_m = tid >> 2;             // 0..63 (and +64)
    const int a_k = (tid & 3) << 2;       // 0,4,8,12
    const float* Ap0 = A + (long)(rowBase + a_m) * K + a_k;
    const float* Ap1 = A + (long)(rowBase + a_m + 64) * K + a_k;

    // --- B tile load mapping ---
    const float* Bp0;
    const float* Bp1;
    int b_k = 0, b_n = 0;
    if constexpr (BNT) {
        // B is [N,K]: transpose [BN x BK] into Bs[k][n]
        Bp0 = B + (long)(colBase + (tid >> 2)) * K + ((tid & 3) << 2);
        Bp1 = Bp0 + 64L * K;
    } else {
        // B is [K,N]: straight copy into Bs[k][n]
        b_k = tid >> 5;              // 0..7 (and +8)
        b_n = (tid & 31) << 2;       // 0..124
        Bp0 = B + (long)b_k * N + colBase + b_n;
        Bp1 = Bp0 + 8L * N;
    }

    float acc[8][8];
#pragma unroll
    for (int i = 0; i < 8; i++)
#pragma unroll
        for (int j = 0; j < 8; j++) acc[i][j] = 0.f;

    // Micro-tile coordinates: rows {ty*4..+3, 64+ty*4..+3}, cols likewise with tx
    const int r0 = ty * 4;
    const int r1 = ty * 4 + 64;
    const int c0 = tx * 4;
    const int c1 = tx * 4 + 64;

    for (int kt = 0; kt < K; kt += BK) {
        // Load A tile (transposed)
        float4 av0 = *(const float4*)(Ap0 + kt);
        float4 av1 = *(const float4*)(Ap1 + kt);
        As[a_k + 0][a_m] = av0.x;
        As[a_k + 1][a_m] = av0.y;
        As[a_k + 2][a_m] = av0.z;
        As[a_k + 3][a_m] = av0.w;
        As[a_k + 0][a_m + 64] = av1.x;
        As[a_k + 1][a_m + 64] = av1.y;
        As[a_k + 2][a_m + 64] = av1.z;
        As[a_k + 3][a_m + 64] = av1.w;

        // Load B tile
        if constexpr (BNT) {
            float4 bv0 = *(const float4*)(Bp0 + kt);
            float4 bv1 = *(const float4*)(Bp1 + kt);
            const int bn = tid >> 2;
            const int bk = (tid & 3) << 2;
            Bs[bk + 0][bn] = bv0.x;
            Bs[bk + 1][bn] = bv0.y;
            Bs[bk + 2][bn] = bv0.z;
            Bs[bk + 3][bn] = bv0.w;
            Bs[bk + 0][bn + 64] = bv1.x;
            Bs[bk + 1][bn + 64] = bv1.y;
            Bs[bk + 2][bn + 64] = bv1.z;
            Bs[bk + 3][bn + 64] = bv1.w;
        } else {
            float4 bv0 = *(const float4*)(Bp0 + (long)kt * N);
            float4 bv1 = *(const float4*)(Bp1 + (long)kt * N);
            *(float4*)&Bs[b_k][b_n] = bv0;
            *(float4*)&Bs[b_k + 8][b_n] = bv1;
        }
        __syncthreads();

#pragma unroll
        for (int kk = 0; kk < BK; ++kk) {
            float a[8], bf[8];
            *(float4*)&a[0]  = *(const float4*)&As[kk][r0];
            *(float4*)&a[4]  = *(const float4*)&As[kk][r1];
            *(float4*)&bf[0] = *(const float4*)&Bs[kk][c0];
            *(float4*)&bf[4] = *(const float4*)&Bs[kk][c1];
#pragma unroll
            for (int i = 0; i < 8; i++)
#pragma unroll
                for (int j = 0; j < 8; j++) acc[i][j] = fmaf(a[i], bf[j], acc[i][j]);
        }
        __syncthreads();
    }

    // Epilogue: alpha scale + optional bias, vectorized stores
    float bvals[8];
    if constexpr (HAS_BIAS) {
        *(float4*)&bvals[0] = *(const float4*)(bias + colBase + c0);
        *(float4*)&bvals[4] = *(const float4*)(bias + colBase + c1);
    } else {
#pragma unroll
        for (int j = 0; j < 8; j++) bvals[j] = 0.f;
    }

#pragma unroll
    for (int i = 0; i < 8; i++) {
        const int row = rowBase + ((i < 4) ? (r0 + i) : (r1 + i - 4));
        float4 o0, o1;
        o0.x = fmaf(acc[i][0], alpha, bvals[0]);
        o0.y = fmaf(acc[i][1], alpha, bvals[1]);
        o0.z = fmaf(acc[i][2], alpha, bvals[2]);
        o0.w = fmaf(acc[i][3], alpha, bvals[3]);
        o1.x = fmaf(acc[i][4], alpha, bvals[4]);
        o1.y = fmaf(acc[i][5], alpha, bvals[5]);
        o1.z = fmaf(acc[i][6], alpha, bvals[6]);
        o1.w = fmaf(acc[i][7], alpha, bvals[7]);
        *(float4*)(C + (long)row * N + colBase + c0) = o0;
        *(float4*)(C + (long)row * N + colBase + c1) = o1;
    }
}

// ----------------------------------------------------------------------------
// Row softmax over last dim (S elements per row), in place.
// One block (256 threads) per row.
// ----------------------------------------------------------------------------
__global__ void softmax_kernel(float* __restrict__ E, int S)
{
    const long row = blockIdx.x;
    float* p = E + row * (long)S;
    __shared__ float red[NTHREADS];
    const int tid = threadIdx.x;

    float m = -1e30f;
    for (int i = tid; i < S; i += NTHREADS) m = fmaxf(m, p[i]);
    red[tid] = m;
    __syncthreads();
#pragma unroll
    for (int s = NTHREADS / 2; s > 0; s >>= 1) {
        if (tid < s) red[tid] = fmaxf(red[tid], red[tid + s]);
        __syncthreads();
    }
    m = red[0];
    __syncthreads();

    float sum = 0.f;
    for (int i = tid; i < S; i += NTHREADS) {
        float e = __expf(p[i] - m);
        p[i] = e;
        sum += e;
    }
    red[tid] = sum;
    __syncthreads();
#pragma unroll
    for (int s = NTHREADS / 2; s > 0; s >>= 1) {
        if (tid < s) red[tid] += red[tid + s];
        __syncthreads();
    }
    const float inv = 1.f / red[0];
    for (int i = tid; i < S; i += NTHREADS) p[i] *= inv;
}

// ----------------------------------------------------------------------------
// Launch
// ----------------------------------------------------------------------------
extern "C" void kernel_launch(void* const* d_in, const int* in_sizes, int n_in,
                              void* d_out, int out_size)
{
    (void)in_sizes; (void)n_in; (void)out_size;

    const float* x  = (const float*)d_in[0];
    const float* wq = (const float*)d_in[1];
    const float* bq = (const float*)d_in[2];
    const float* wk = (const float*)d_in[3];
    const float* bk = (const float*)d_in[4];
    const float* wv = (const float*)d_in[5];
    const float* bv = (const float*)d_in[6];
    const float* wo = (const float*)d_in[7];
    const float* bo = (const float*)d_in[8];
    float* out = (float*)d_out;

    float *q, *k, *v, *ctx, *e;
    cudaGetSymbolAddress((void**)&q,   g_q);
    cudaGetSymbolAddress((void**)&k,   g_k);
    cudaGetSymbolAddress((void**)&v,   g_v);
    cudaGetSymbolAddress((void**)&ctx, g_ctx);
    cudaGetSymbolAddress((void**)&e,   g_e);

    const int Bsz = 8, S = 2048, H = 1024;
    const int MS = Bsz * S;  // 16384
    const float scale = 0.03125f;  // 1/sqrt(1024)

    dim3 blk(NTHREADS);
    dim3 gProj(H / BN, MS / BM, 1);      // (8, 128, 1)

    // QKV projections: [16384,1024] @ [1024,1024] + bias
    sgemm_kernel<false, true><<<gProj, blk>>>(x, wq, bq, q, MS, H, H, 0, 0, 0, 1.f);
    sgemm_kernel<false, true><<<gProj, blk>>>(x, wk, bk, k, MS, H, H, 0, 0, 0, 1.f);
    sgemm_kernel<false, true><<<gProj, blk>>>(x, wv, bv, v, MS, H, H, 0, 0, 0, 1.f);

    // Energy: E[b] = scale * Q[b] @ K[b]^T   -> [8][2048,2048]
    dim3 gE(S / BN, S / BM, Bsz);        // (16, 16, 8)
    sgemm_kernel<true, false><<<gE, blk>>>(q, k, nullptr, e, S, S, H,
                                           (long)S * H, (long)S * H, (long)S * S, scale);

    // Softmax over rows of E
    softmax_kernel<<<Bsz * S, NTHREADS>>>(e, S);

    // Context: C[b] = E[b] @ V[b]   -> [8][2048,1024]
    dim3 gC(H / BN, S / BM, Bsz);        // (8, 16, 8)
    sgemm_kernel<false, false><<<gC, blk>>>(e, v, nullptr, ctx, S, H, S,
                                            (long)S * S, (long)S * H, (long)S * H, 1.f);

    // Output projection: out = C @ Wo + bo
    sgemm_kernel<false, true><<<gProj, blk>>>(ctx, wo, bo, out, MS, H, H, 0, 0, 0, 1.f);
}

// round 3
// speedup vs baseline: 2.5806x; 2.5806x over previous
#include <cuda_runtime.h>
#include <cstdint>

// ============================================================================
// SpecAttn via mma.sync tf32 (HMMA) — the compute_103 virtual arch used by the
// harness cannot express tcgen05, so we use the arch-agnostic tensor-core path.
// 5 GEMMs (128x128 tile, BK=16, 4-stage cp.async, tf32 m16n8k8 MMA) +
// transposes + softmax. All MMA inputs pre-rounded to tf32 (cvt.rna).
// ============================================================================

#define BM 128
#define BN 128
#define BK 16
#define ST 4
#define PAD 4
#define ROWF (BK + PAD)          // 20 floats per smem row
#define TILE_F (BM * ROWF)       // 2560 floats per operand tile
#define STAGE_F (2 * TILE_F)     // A + B per stage
#define SMEM_BYTES (ST * STAGE_F * 4)   // 81920 B

// ---------------- scratch (device globals; no allocations) ------------------
__device__ float g_xc [8L*2048*1024];
__device__ float g_q  [8L*2048*1024];
__device__ float g_k  [8L*2048*1024];
__device__ float g_v  [8L*2048*1024];
__device__ float g_vt [8L*2048*1024];
__device__ float g_ctx[8L*2048*1024];
__device__ float g_e  [8L*2048*2048];
__device__ float g_wqT[1024L*1024];
__device__ float g_wkT[1024L*1024];
__device__ float g_wvT[1024L*1024];
__device__ float g_woT[1024L*1024];

// ---------------- helpers ----------------------------------------------------
__device__ __forceinline__ uint32_t smem_u32(const void* p) {
    uint32_t a;
    asm("{ .reg .u64 t; cvta.to.shared.u64 t, %1; cvt.u32.u64 %0, t; }" : "=r"(a) : "l"(p));
    return a;
}
__device__ __forceinline__ float to_tf32(float x) {
    uint32_t u;
    asm("cvt.rna.tf32.f32 %0, %1;" : "=r"(u) : "f"(x));
    return __uint_as_float(u);
}
__device__ __forceinline__ void mma_tf32(float* c, const uint32_t* a, const uint32_t* b) {
    asm volatile(
        "mma.sync.aligned.m16n8k8.row.col.f32.tf32.tf32.f32 "
        "{%0,%1,%2,%3},{%4,%5,%6,%7},{%8,%9},{%0,%1,%2,%3};"
        : "+f"(c[0]), "+f"(c[1]), "+f"(c[2]), "+f"(c[3])
        : "r"(a[0]), "r"(a[1]), "r"(a[2]), "r"(a[3]), "r"(b[0]), "r"(b[1]));
}
__device__ __forceinline__ uint32_t fbits(float x) { return __float_as_uint(x); }

// ============================================================================
// tf32 GEMM: C[z] = alpha * A[z] @ B[z]^T (+ bias, + optional tf32 round)
//   A: [M,K] row-major.  B: [N,K] row-major (K-major).  M,N mult of 128, K of 16.
// grid = (N/BN, M/BM, Z), block = 256.
// ============================================================================
template <bool HAS_BIAS, bool CVT_OUT>
__global__ __launch_bounds__(256, 2)
void tf32_gemm(const float* __restrict__ A, const float* __restrict__ Bm,
               const float* __restrict__ bias, float* __restrict__ C,
               int K, int N, long sA, long sB, long sC, float alpha)
{
    extern __shared__ float smf[];
    const uint32_t sbase = smem_u32(smf);
    const int tid = threadIdx.x;

    A  += (long)blockIdx.z * sA;
    Bm += (long)blockIdx.z * sB;
    C  += (long)blockIdx.z * sC;
    const long rowBase = (long)blockIdx.y * BM;
    const long colBase = (long)blockIdx.x * BN;

    // ---- global->smem mapping: chunk c (0..511): row=c>>2, seg=c&3 (16B) ----
    const int c0r = tid >> 2, c0s = tid & 3;          // chunk tid
    const int c1r = (tid + 256) >> 2;                 // chunk tid+256 (seg same)
    const uint32_t aoff0 = (uint32_t)(c0r * ROWF + c0s * 4) * 4;
    const uint32_t aoff1 = (uint32_t)(c1r * ROWF + c0s * 4) * 4;
    const float* Ag0 = A + (rowBase + c0r) * (long)K + c0s * 4;
    const float* Ag1 = A + (rowBase + c1r) * (long)K + c0s * 4;
    const float* Bg0 = Bm + (colBase + c0r) * (long)K + c0s * 4;
    const float* Bg1 = Bm + (colBase + c1r) * (long)K + c0s * 4;

    const int NT = K >> 4;

#define LOAD_STAGE(sbuf, kt) do {                                              \
    const uint32_t st_ = sbase + (uint32_t)(sbuf) * (STAGE_F * 4);             \
    const uint32_t bt_ = st_ + TILE_F * 4;                                     \
    const long ko_ = (long)(kt) * BK;                                          \
    asm volatile("cp.async.cg.shared.global [%0],[%1],16;" :: "r"(st_ + aoff0), "l"(Ag0 + ko_) : "memory"); \
    asm volatile("cp.async.cg.shared.global [%0],[%1],16;" :: "r"(st_ + aoff1), "l"(Ag1 + ko_) : "memory"); \
    asm volatile("cp.async.cg.shared.global [%0],[%1],16;" :: "r"(bt_ + aoff0), "l"(Bg0 + ko_) : "memory"); \
    asm volatile("cp.async.cg.shared.global [%0],[%1],16;" :: "r"(bt_ + aoff1), "l"(Bg1 + ko_) : "memory"); \
} while (0)

    // prologue: stages 0..ST-2
    #pragma unroll
    for (int s = 0; s < ST - 1; ++s) {
        LOAD_STAGE(s, s);
        asm volatile("cp.async.commit_group;" ::: "memory");
    }

    // ---- warp/thread tiling ----
    const int warp = tid >> 5, lane = tid & 31;
    const int grp = lane >> 2, tg = lane & 3;
    const int mbase = (warp & 3) * 32;    // 4 warps over M
    const int nbase = (warp >> 2) * 64;   // 2 warps over N

    float acc[2][8][4];
    #pragma unroll
    for (int mt = 0; mt < 2; mt++)
        #pragma unroll
        for (int nt = 0; nt < 8; nt++)
            #pragma unroll
            for (int j = 0; j < 4; j++) acc[mt][nt][j] = 0.f;

    for (int t = 0; t < NT; ++t) {
        if (t + ST - 1 < NT) LOAD_STAGE((t + ST - 1) & (ST - 1), t + ST - 1);
        asm volatile("cp.async.commit_group;" ::: "memory");
        asm volatile("cp.async.wait_group %0;" :: "n"(ST - 1) : "memory");
        __syncthreads();

        const float* sA = smf + (t & (ST - 1)) * STAGE_F;
        const float* sB = sA + TILE_F;

        #pragma unroll
        for (int k8 = 0; k8 < BK; k8 += 8) {
            uint32_t a[2][4], b[8][2];
            #pragma unroll
            for (int mt = 0; mt < 2; mt++) {
                const float* p = sA + (mbase + mt * 16 + grp) * ROWF + k8 + tg;
                a[mt][0] = fbits(p[0]);
                a[mt][1] = fbits(p[8 * ROWF]);
                a[mt][2] = fbits(p[4]);
                a[mt][3] = fbits(p[8 * ROWF + 4]);
            }
            #pragma unroll
            for (int nt = 0; nt < 8; nt++) {
                const float* p = sB + (nbase + nt * 8 + grp) * ROWF + k8 + tg;
                b[nt][0] = fbits(p[0]);
                b[nt][1] = fbits(p[4]);
            }
            #pragma unroll
            for (int mt = 0; mt < 2; mt++)
                #pragma unroll
                for (int nt = 0; nt < 8; nt++)
                    mma_tf32(acc[mt][nt], a[mt], b[nt]);
        }
        __syncthreads();
    }

    // ---- epilogue ----
    #pragma unroll
    for (int nt = 0; nt < 8; nt++) {
        const long col = colBase + nbase + nt * 8 + tg * 2;
        float2 bv = make_float2(0.f, 0.f);
        if (HAS_BIAS) bv = *(const float2*)(bias + col);
        #pragma unroll
        for (int mt = 0; mt < 2; mt++) {
            const long r0 = rowBase + mbase + mt * 16 + grp;
            float o0 = acc[mt][nt][0] * alpha + bv.x;
            float o1 = acc[mt][nt][1] * alpha + bv.y;
            float o2 = acc[mt][nt][2] * alpha + bv.x;
            float o3 = acc[mt][nt][3] * alpha + bv.y;
            if (CVT_OUT) {
                o0 = to_tf32(o0); o1 = to_tf32(o1);
                o2 = to_tf32(o2); o3 = to_tf32(o3);
            }
            *(float2*)(C + r0 * N + col)       = make_float2(o0, o1);
            *(float2*)(C + (r0 + 8) * N + col) = make_float2(o2, o3);
        }
    }
#undef LOAD_STAGE
}

// ============================================================================
// transpose + tf32 round: dst[c][r] = tf32(src[r][c]).  grid(cols/32, rows/32, Z)
// ============================================================================
__global__ __launch_bounds__(256)
void transpose_kernel(const float* __restrict__ src, float* __restrict__ dst,
                      int rows, int cols)
{
    __shared__ float tile[32][33];
    const long zoff = (long)blockIdx.z * rows * (long)cols;
    src += zoff; dst += zoff;
    const int c0 = blockIdx.x * 32, r0 = blockIdx.y * 32;
    const int tx = threadIdx.x, ty = threadIdx.y;
    #pragma unroll
    for (int i = ty; i < 32; i += 8)
        tile[i][tx] = to_tf32(src[(long)(r0 + i) * cols + c0 + tx]);
    __syncthreads();
    #pragma unroll
    for (int i = ty; i < 32; i += 8)
        dst[(long)(c0 + i) * rows + r0 + tx] = tile[tx][i];
}

// elementwise tf32 round (for x)
__global__ __launch_bounds__(256)
void cvt_kernel(const float4* __restrict__ in, float4* __restrict__ out, long n4)
{
    long i = blockIdx.x * 256L + threadIdx.x;
    const long stride = gridDim.x * 256L;
    for (; i < n4; i += stride) {
        float4 v = in[i];
        v.x = to_tf32(v.x); v.y = to_tf32(v.y);
        v.z = to_tf32(v.z); v.w = to_tf32(v.w);
        out[i] = v;
    }
}

// ============================================================================
// single-pass row softmax (rows of 2048) + tf32 round. grid = B*S, block = 256.
// ============================================================================
__global__ __launch_bounds__(256)
void softmax_kernel(float* __restrict__ E)
{
    float4* p = (float4*)(E + (long)blockIdx.x * 2048);
    const int tid = threadIdx.x;
    __shared__ float red[8];
    float4 a = p[tid], b = p[tid + 256];

    float m = fmaxf(fmaxf(fmaxf(a.x, a.y), fmaxf(a.z, a.w)),
                    fmaxf(fmaxf(b.x, b.y), fmaxf(b.z, b.w)));
    #pragma unroll
    for (int s = 16; s > 0; s >>= 1) m = fmaxf(m, __shfl_xor_sync(~0u, m, s));
    if ((tid & 31) == 0) red[tid >> 5] = m;
    __syncthreads();
    m = red[0];
    #pragma unroll
    for (int i = 1; i < 8; i++) m = fmaxf(m, red[i]);
    __syncthreads();

    a.x = __expf(a.x - m); a.y = __expf(a.y - m);
    a.z = __expf(a.z - m); a.w = __expf(a.w - m);
    b.x = __expf(b.x - m); b.y = __expf(b.y - m);
    b.z = __expf(b.z - m); b.w = __expf(b.w - m);
    float s8 = a.x + a.y + a.z + a.w + b.x + b.y + b.z + b.w;
    #pragma unroll
    for (int s = 16; s > 0; s >>= 1) s8 += __shfl_xor_sync(~0u, s8, s);
    if ((tid & 31) == 0) red[tid >> 5] = s8;
    __syncthreads();
    float tot = 0.f;
    #pragma unroll
    for (int i = 0; i < 8; i++) tot += red[i];
    const float inv = 1.f / tot;

    a.x = to_tf32(a.x * inv); a.y = to_tf32(a.y * inv);
    a.z = to_tf32(a.z * inv); a.w = to_tf32(a.w * inv);
    b.x = to_tf32(b.x * inv); b.y = to_tf32(b.y * inv);
    b.z = to_tf32(b.z * inv); b.w = to_tf32(b.w * inv);
    p[tid] = a; p[tid + 256] = b;
}

// ============================================================================
extern "C" void kernel_launch(void* const* d_in, const int* in_sizes, int n_in,
                              void* d_out, int out_size)
{
    (void)in_sizes; (void)n_in; (void)out_size;
    const float* x  = (const float*)d_in[0];
    const float* wq = (const float*)d_in[1];
    const float* bq = (const float*)d_in[2];
    const float* wk = (const float*)d_in[3];
    const float* bk = (const float*)d_in[4];
    const float* wv = (const float*)d_in[5];
    const float* bv = (const float*)d_in[6];
    const float* wo = (const float*)d_in[7];
    const float* bo = (const float*)d_in[8];
    float* out = (float*)d_out;

    float *xc, *q, *k, *v, *vt, *ctx, *e, *wqT, *wkT, *wvT, *woT;
    cudaGetSymbolAddress((void**)&xc,  g_xc);
    cudaGetSymbolAddress((void**)&q,   g_q);
    cudaGetSymbolAddress((void**)&k,   g_k);
    cudaGetSymbolAddress((void**)&v,   g_v);
    cudaGetSymbolAddress((void**)&vt,  g_vt);
    cudaGetSymbolAddress((void**)&ctx, g_ctx);
    cudaGetSymbolAddress((void**)&e,   g_e);
    cudaGetSymbolAddress((void**)&wqT, g_wqT);
    cudaGetSymbolAddress((void**)&wkT, g_wkT);
    cudaGetSymbolAddress((void**)&wvT, g_wvT);
    cudaGetSymbolAddress((void**)&woT, g_woT);

    cudaFuncSetAttribute(tf32_gemm<true,  true >, cudaFuncAttributeMaxDynamicSharedMemorySize, SMEM_BYTES);
    cudaFuncSetAttribute(tf32_gemm<true,  false>, cudaFuncAttributeMaxDynamicSharedMemorySize, SMEM_BYTES);
    cudaFuncSetAttribute(tf32_gemm<false, true >, cudaFuncAttributeMaxDynamicSharedMemorySize, SMEM_BYTES);
    cudaFuncSetAttribute(tf32_gemm<false, false>, cudaFuncAttributeMaxDynamicSharedMemorySize, SMEM_BYTES);

    const int Bsz = 8, S = 2048, H = 1024;
    const int MS = Bsz * S;                 // 16384
    const float scale = 0.03125f;           // 1/sqrt(1024)

    // pre-round x to tf32
    cvt_kernel<<<1024, 256>>>((const float4*)x, (float4*)xc, (long)MS * H / 4);

    dim3 tb(32, 8);
    transpose_kernel<<<dim3(32, 32, 1), tb>>>(wq, wqT, H, H);
    transpose_kernel<<<dim3(32, 32, 1), tb>>>(wk, wkT, H, H);
    transpose_kernel<<<dim3(32, 32, 1), tb>>>(wv, wvT, H, H);
    transpose_kernel<<<dim3(32, 32, 1), tb>>>(wo, woT, H, H);

    dim3 blk(256);
    dim3 gProj(H / BN, MS / BM, 1);   // (8, 128)

    // QKV projections (outputs rounded to tf32 for the next GEMMs)
    tf32_gemm<true, true><<<gProj, blk, SMEM_BYTES>>>(xc, wqT, bq, q, H, H, 0, 0, 0, 1.f);
    tf32_gemm<true, true><<<gProj, blk, SMEM_BYTES>>>(xc, wkT, bk, k, H, H, 0, 0, 0, 1.f);
    tf32_gemm<true, true><<<gProj, blk, SMEM_BYTES>>>(xc, wvT, bv, v, H, H, 0, 0, 0, 1.f);

    // V transpose per batch: [S,H] -> [H,S]
    transpose_kernel<<<dim3(H / 32, S / 32, Bsz), tb>>>(v, vt, S, H);

    // Energy: E = scale * Q @ K^T
    tf32_gemm<false, false><<<dim3(S / BN, S / BM, Bsz), blk, SMEM_BYTES>>>(
        q, k, nullptr, e, H, S, (long)S * H, (long)S * H, (long)S * S, scale);

    softmax_kernel<<<MS, 256>>>(e);

    // Context: ctx = softmax(E) @ V
    tf32_gemm<false, true><<<dim3(H / BN, S / BM, Bsz), blk, SMEM_BYTES>>>(
        e, vt, nullptr, ctx, S, H, (long)S * S, (long)H * S, (long)S * H, 1.f);

    // Output projection
    tf32_gemm<true, false><<<gProj, blk, SMEM_BYTES>>>(ctx, woT, bo, out, H, H, 0, 0, 0, 1.f);
}

// round 4
// speedup vs baseline: 3.0128x; 1.1675x over previous
#include <cuda_runtime.h>
#include <cstdint>

// ============================================================================
// SpecAttn via mma.sync tf32 (HMMA). R4: smem-bandwidth-aware GEMM —
// 128x128 tile, 4 warps (2x2 grid, 64x64 warp tiles), BK=32, 2-stage
// cp.async double buffer, ONE __syncthreads per K-iteration.
// ============================================================================

#define BM 128
#define BN 128
#define BK 32
#define ST 2
#define PAD 4
#define ROWF (BK + PAD)            // 36 floats per smem row
#define TILE_F (BM * ROWF)         // 4608 floats per operand tile
#define STAGE_F (2 * TILE_F)       // A + B per stage
#define SMEM_BYTES (ST * STAGE_F * 4)   // 73728 B

// ---------------- scratch (device globals; no allocations) ------------------
__device__ float g_xc [8L*2048*1024];
__device__ float g_q  [8L*2048*1024];
__device__ float g_k  [8L*2048*1024];
__device__ float g_v  [8L*2048*1024];
__device__ float g_vt [8L*2048*1024];
__device__ float g_ctx[8L*2048*1024];
__device__ float g_e  [8L*2048*2048];
__device__ float g_wqT[1024L*1024];
__device__ float g_wkT[1024L*1024];
__device__ float g_wvT[1024L*1024];
__device__ float g_woT[1024L*1024];

// ---------------- helpers ----------------------------------------------------
__device__ __forceinline__ uint32_t smem_u32(const void* p) {
    uint32_t a;
    asm("{ .reg .u64 t; cvta.to.shared.u64 t, %1; cvt.u32.u64 %0, t; }" : "=r"(a) : "l"(p));
    return a;
}
__device__ __forceinline__ float to_tf32(float x) {
    uint32_t u;
    asm("cvt.rna.tf32.f32 %0, %1;" : "=r"(u) : "f"(x));
    return __uint_as_float(u);
}
__device__ __forceinline__ void mma_tf32(float* c, const uint32_t* a, const uint32_t* b) {
    asm volatile(
        "mma.sync.aligned.m16n8k8.row.col.f32.tf32.tf32.f32 "
        "{%0,%1,%2,%3},{%4,%5,%6,%7},{%8,%9},{%0,%1,%2,%3};"
        : "+f"(c[0]), "+f"(c[1]), "+f"(c[2]), "+f"(c[3])
        : "r"(a[0]), "r"(a[1]), "r"(a[2]), "r"(a[3]), "r"(b[0]), "r"(b[1]));
}
__device__ __forceinline__ uint32_t fbits(float x) { return __float_as_uint(x); }

// ============================================================================
// tf32 GEMM: C[z] = alpha * A[z] @ B[z]^T (+ bias, + optional tf32 round)
//   A: [M,K] row-major.  B: [N,K] row-major.  M,N mult of 128, K mult of 32.
// grid = (N/BN, M/BM, Z), block = 128 (4 warps, 2x2 warp grid).
// ============================================================================
template <bool HAS_BIAS, bool CVT_OUT>
__global__ __launch_bounds__(128, 2)
void tf32_gemm(const float* __restrict__ A, const float* __restrict__ Bm,
               const float* __restrict__ bias, float* __restrict__ C,
               int K, int N, long sA, long sB, long sC, float alpha)
{
    extern __shared__ float smf[];
    const uint32_t sbase = smem_u32(smf);
    const int tid = threadIdx.x;

    A  += (long)blockIdx.z * sA;
    Bm += (long)blockIdx.z * sB;
    C  += (long)blockIdx.z * sC;
    const long rowBase = (long)blockIdx.y * BM;
    const long colBase = (long)blockIdx.x * BN;

    // ---- global->smem mapping: thread covers rows (tid>>3)+16i, seg tid&7 ----
    const int lr = tid >> 3;           // 0..15
    const int ls = tid & 7;            // 16B segment within 128B row
    const uint32_t off0 = (uint32_t)(lr * ROWF + ls * 4) * 4;
    const float* Ag = A  + (rowBase + lr) * (long)K + ls * 4;
    const float* Bg = Bm + (colBase + lr) * (long)K + ls * 4;

    const int NT = K >> 5;

#define LOAD_STAGE(sbuf, kt) do {                                              \
    const uint32_t st_ = sbase + (uint32_t)(sbuf) * (STAGE_F * 4);             \
    const uint32_t bt_ = st_ + TILE_F * 4;                                     \
    const long ko_ = (long)(kt) * BK;                                          \
    for (int i_ = 0; i_ < 8; i_++) {                                           \
        asm volatile("cp.async.cg.shared.global [%0],[%1],16;"                 \
            :: "r"(st_ + off0 + (uint32_t)i_ * (16 * ROWF * 4)),               \
               "l"(Ag + ko_ + (long)16 * i_ * K) : "memory");                  \
        asm volatile("cp.async.cg.shared.global [%0],[%1],16;"                 \
            :: "r"(bt_ + off0 + (uint32_t)i_ * (16 * ROWF * 4)),               \
               "l"(Bg + ko_ + (long)16 * i_ * K) : "memory");                  \
    }                                                                          \
    asm volatile("cp.async.commit_group;" ::: "memory");                       \
} while (0)

    // prologue
    LOAD_STAGE(0, 0);

    // ---- warp/thread tiling: 2x2 warp grid, 64x64 per warp ----
    const int warp = tid >> 5, lane = tid & 31;
    const int grp = lane >> 2, tg = lane & 3;
    const int mbase = (warp & 1) * 64;
    const int nbase = (warp >> 1) * 64;

    float acc[4][8][4];
    #pragma unroll
    for (int mt = 0; mt < 4; mt++)
        #pragma unroll
        for (int nt = 0; nt < 8; nt++)
            #pragma unroll
            for (int j = 0; j < 4; j++) acc[mt][nt][j] = 0.f;

    for (int t = 0; t < NT; ++t) {
        asm volatile("cp.async.wait_group 0;" ::: "memory");
        __syncthreads();
        if (t + 1 < NT) LOAD_STAGE((t + 1) & 1, t + 1);

        const float* sAt = smf + (t & 1) * STAGE_F;
        const float* sBt = sAt + TILE_F;

        #pragma unroll
        for (int k8 = 0; k8 < BK; k8 += 8) {
            uint32_t a[4][4], b[8][2];
            #pragma unroll
            for (int mt = 0; mt < 4; mt++) {
                const float* p = sAt + (mbase + mt * 16 + grp) * ROWF + k8 + tg;
                a[mt][0] = fbits(p[0]);
                a[mt][1] = fbits(p[8 * ROWF]);
                a[mt][2] = fbits(p[4]);
                a[mt][3] = fbits(p[8 * ROWF + 4]);
            }
            #pragma unroll
            for (int nt = 0; nt < 8; nt++) {
                const float* p = sBt + (nbase + nt * 8 + grp) * ROWF + k8 + tg;
                b[nt][0] = fbits(p[0]);
                b[nt][1] = fbits(p[4]);
            }
            #pragma unroll
            for (int mt = 0; mt < 4; mt++)
                #pragma unroll
                for (int nt = 0; nt < 8; nt++)
                    mma_tf32(acc[mt][nt], a[mt], b[nt]);
        }
    }

    // ---- epilogue ----
    #pragma unroll
    for (int nt = 0; nt < 8; nt++) {
        const long col = colBase + nbase + nt * 8 + tg * 2;
        float2 bv = make_float2(0.f, 0.f);
        if (HAS_BIAS) bv = *(const float2*)(bias + col);
        #pragma unroll
        for (int mt = 0; mt < 4; mt++) {
            const long r0 = rowBase + mbase + mt * 16 + grp;
            float o0 = acc[mt][nt][0] * alpha + bv.x;
            float o1 = acc[mt][nt][1] * alpha + bv.y;
            float o2 = acc[mt][nt][2] * alpha + bv.x;
            float o3 = acc[mt][nt][3] * alpha + bv.y;
            if (CVT_OUT) {
                o0 = to_tf32(o0); o1 = to_tf32(o1);
                o2 = to_tf32(o2); o3 = to_tf32(o3);
            }
            *(float2*)(C + r0 * N + col)       = make_float2(o0, o1);
            *(float2*)(C + (r0 + 8) * N + col) = make_float2(o2, o3);
        }
    }
#undef LOAD_STAGE
}

// ============================================================================
// transpose + tf32 round: dst[c][r] = tf32(src[r][c]).  grid(cols/32, rows/32, Z)
// ============================================================================
__global__ __launch_bounds__(256)
void transpose_kernel(const float* __restrict__ src, float* __restrict__ dst,
                      int rows, int cols)
{
    __shared__ float tile[32][33];
    const long zoff = (long)blockIdx.z * rows * (long)cols;
    src += zoff; dst += zoff;
    const int c0 = blockIdx.x * 32, r0 = blockIdx.y * 32;
    const int tx = threadIdx.x, ty = threadIdx.y;
    #pragma unroll
    for (int i = ty; i < 32; i += 8)
        tile[i][tx] = to_tf32(src[(long)(r0 + i) * cols + c0 + tx]);
    __syncthreads();
    #pragma unroll
    for (int i = ty; i < 32; i += 8)
        dst[(long)(c0 + i) * rows + r0 + tx] = tile[tx][i];
}

// elementwise tf32 round (for x)
__global__ __launch_bounds__(256)
void cvt_kernel(const float4* __restrict__ in, float4* __restrict__ out, long n4)
{
    long i = blockIdx.x * 256L + threadIdx.x;
    const long stride = gridDim.x * 256L;
    for (; i < n4; i += stride) {
        float4 v = in[i];
        v.x = to_tf32(v.x); v.y = to_tf32(v.y);
        v.z = to_tf32(v.z); v.w = to_tf32(v.w);
        out[i] = v;
    }
}

// ============================================================================
// single-pass row softmax (rows of 2048) + tf32 round. grid = B*S, block = 256.
// ============================================================================
__global__ __launch_bounds__(256)
void softmax_kernel(float* __restrict__ E)
{
    float4* p = (float4*)(E + (long)blockIdx.x * 2048);
    const int tid = threadIdx.x;
    __shared__ float red[8];
    float4 a = p[tid], b = p[tid + 256];

    float m = fmaxf(fmaxf(fmaxf(a.x, a.y), fmaxf(a.z, a.w)),
                    fmaxf(fmaxf(b.x, b.y), fmaxf(b.z, b.w)));
    #pragma unroll
    for (int s = 16; s > 0; s >>= 1) m = fmaxf(m, __shfl_xor_sync(~0u, m, s));
    if ((tid & 31) == 0) red[tid >> 5] = m;
    __syncthreads();
    m = red[0];
    #pragma unroll
    for (int i = 1; i < 8; i++) m = fmaxf(m, red[i]);
    __syncthreads();

    a.x = __expf(a.x - m); a.y = __expf(a.y - m);
    a.z = __expf(a.z - m); a.w = __expf(a.w - m);
    b.x = __expf(b.x - m); b.y = __expf(b.y - m);
    b.z = __expf(b.z - m); b.w = __expf(b.w - m);
    float s8 = a.x + a.y + a.z + a.w + b.x + b.y + b.z + b.w;
    #pragma unroll
    for (int s = 16; s > 0; s >>= 1) s8 += __shfl_xor_sync(~0u, s8, s);
    if ((tid & 31) == 0) red[tid >> 5] = s8;
    __syncthreads();
    float tot = 0.f;
    #pragma unroll
    for (int i = 0; i < 8; i++) tot += red[i];
    const float inv = 1.f / tot;

    a.x = to_tf32(a.x * inv); a.y = to_tf32(a.y * inv);
    a.z = to_tf32(a.z * inv); a.w = to_tf32(a.w * inv);
    b.x = to_tf32(b.x * inv); b.y = to_tf32(b.y * inv);
    b.z = to_tf32(b.z * inv); b.w = to_tf32(b.w * inv);
    p[tid] = a; p[tid + 256] = b;
}

// ============================================================================
extern "C" void kernel_launch(void* const* d_in, const int* in_sizes, int n_in,
                              void* d_out, int out_size)
{
    (void)in_sizes; (void)n_in; (void)out_size;
    const float* x  = (const float*)d_in[0];
    const float* wq = (const float*)d_in[1];
    const float* bq = (const float*)d_in[2];
    const float* wk = (const float*)d_in[3];
    const float* bk = (const float*)d_in[4];
    const float* wv = (const float*)d_in[5];
    const float* bv = (const float*)d_in[6];
    const float* wo = (const float*)d_in[7];
    const float* bo = (const float*)d_in[8];
    float* out = (float*)d_out;

    float *xc, *q, *k, *v, *vt, *ctx, *e, *wqT, *wkT, *wvT, *woT;
    cudaGetSymbolAddress((void**)&xc,  g_xc);
    cudaGetSymbolAddress((void**)&q,   g_q);
    cudaGetSymbolAddress((void**)&k,   g_k);
    cudaGetSymbolAddress((void**)&v,   g_v);
    cudaGetSymbolAddress((void**)&vt,  g_vt);
    cudaGetSymbolAddress((void**)&ctx, g_ctx);
    cudaGetSymbolAddress((void**)&e,   g_e);
    cudaGetSymbolAddress((void**)&wqT, g_wqT);
    cudaGetSymbolAddress((void**)&wkT, g_wkT);
    cudaGetSymbolAddress((void**)&wvT, g_wvT);
    cudaGetSymbolAddress((void**)&woT, g_woT);

    cudaFuncSetAttribute(tf32_gemm<true,  true >, cudaFuncAttributeMaxDynamicSharedMemorySize, SMEM_BYTES);
    cudaFuncSetAttribute(tf32_gemm<true,  false>, cudaFuncAttributeMaxDynamicSharedMemorySize, SMEM_BYTES);
    cudaFuncSetAttribute(tf32_gemm<false, true >, cudaFuncAttributeMaxDynamicSharedMemorySize, SMEM_BYTES);
    cudaFuncSetAttribute(tf32_gemm<false, false>, cudaFuncAttributeMaxDynamicSharedMemorySize, SMEM_BYTES);

    const int Bsz = 8, S = 2048, H = 1024;
    const int MS = Bsz * S;                 // 16384
    const float scale = 0.03125f;           // 1/sqrt(1024)

    // pre-round x to tf32
    cvt_kernel<<<1024, 256>>>((const float4*)x, (float4*)xc, (long)MS * H / 4);

    dim3 tb(32, 8);
    transpose_kernel<<<dim3(32, 32, 1), tb>>>(wq, wqT, H, H);
    transpose_kernel<<<dim3(32, 32, 1), tb>>>(wk, wkT, H, H);
    transpose_kernel<<<dim3(32, 32, 1), tb>>>(wv, wvT, H, H);
    transpose_kernel<<<dim3(32, 32, 1), tb>>>(wo, woT, H, H);

    dim3 blk(128);
    dim3 gProj(H / BN, MS / BM, 1);   // (8, 128)

    // QKV projections (outputs rounded to tf32 for the next GEMMs)
    tf32_gemm<true, true><<<gProj, blk, SMEM_BYTES>>>(xc, wqT, bq, q, H, H, 0, 0, 0, 1.f);
    tf32_gemm<true, true><<<gProj, blk, SMEM_BYTES>>>(xc, wkT, bk, k, H, H, 0, 0, 0, 1.f);
    tf32_gemm<true, true><<<gProj, blk, SMEM_BYTES>>>(xc, wvT, bv, v, H, H, 0, 0, 0, 1.f);

    // V transpose per batch: [S,H] -> [H,S]
    transpose_kernel<<<dim3(H / 32, S / 32, Bsz), tb>>>(v, vt, S, H);

    // Energy: E = scale * Q @ K^T
    tf32_gemm<false, false><<<dim3(S / BN, S / BM, Bsz), blk, SMEM_BYTES>>>(
        q, k, nullptr, e, H, S, (long)S * H, (long)S * H, (long)S * S, scale);

    softmax_kernel<<<MS, 256>>>(e);

    // Context: ctx = softmax(E) @ V
    tf32_gemm<false, true><<<dim3(H / BN, S / BM, Bsz), blk, SMEM_BYTES>>>(
        e, vt, nullptr, ctx, S, H, (long)S * S, (long)H * S, (long)S * H, 1.f);

    // Output projection
    tf32_gemm<true, false><<<gProj, blk, SMEM_BYTES>>>(ctx, woT, bo, out, H, H, 0, 0, 0, 1.f);
}